// round 8
// baseline (speedup 1.0000x reference)
#include <cuda_runtime.h>
#include <cuda_bf16.h>
#include <cstdint>

// ---------------- problem constants ----------------
#define B_ROWS 4096
#define C_CLS  1000
#define NN     8192
#define DD     256

// main kernel tiling
#define MCTA    128                 // adj rows per CTA
#define KSPLIT  2
#define KC      32                  // K per pipeline stage
#define KRANGE  (NN / KSPLIT)       // 4096
#define NIT     (KRANGE / KC)       // 128
#define NCTA    ((NN / MCTA) * KSPLIT)  // 128
#define THREADS 512

// smem: A fp32 [128][36] x3, B bf16 [256][40] x5, A' bf16 [128][40] x2
#define A_STRIDE_F 36
#define P_STRIDE_H 40
#define ASZ   (MCTA * A_STRIDE_F * 4)     // 18432
#define BSZ   (DD * P_STRIDE_H * 2)       // 20480
#define APSZ  (MCTA * P_STRIDE_H * 2)     // 10240
#define BOFF  (3 * ASZ)                   // 55296
#define APOFF (BOFF + 5 * BSZ)            // 157696
#define SMEM_BYTES (APOFF + 2 * APSZ)     // 178176

// ---------------- device scratch ----------------
__device__ __nv_bfloat16 g_ehatT[(size_t)DD * NN];  // Ê^T [256][8192] bf16
__device__ float g_ce[B_ROWS];
__device__ float g_psem[NCTA];
__device__ float g_pabs[NCTA];
__device__ float g_pplain[NCTA];
__device__ int   g_tgt64;

// ---------------- helpers ----------------
__device__ __forceinline__ uint32_t smem_u32(const void* p) {
    uint32_t a;
    asm("{ .reg .u64 t; cvta.to.shared.u64 t, %1; cvt.u32.u64 %0, t; }" : "=r"(a) : "l"(p));
    return a;
}
__device__ __forceinline__ void cp16(uint32_t s, const void* g) {
    asm volatile("cp.async.cg.shared.global [%0], [%1], 16;" :: "r"(s), "l"(g));
}
__device__ __forceinline__ void cp_commit() {
    asm volatile("cp.async.commit_group;" ::: "memory");
}
__device__ __forceinline__ void ldm_x4(uint32_t* r, uint32_t addr) {
    asm volatile("ldmatrix.sync.aligned.m8n8.x4.shared.b16 {%0,%1,%2,%3}, [%4];"
                 : "=r"(r[0]), "=r"(r[1]), "=r"(r[2]), "=r"(r[3]) : "r"(addr));
}
__device__ __forceinline__ void mma_16816(float* d, const uint32_t* a,
                                          uint32_t b0, uint32_t b1) {
    asm volatile(
        "mma.sync.aligned.m16n8k16.row.col.f32.bf16.bf16.f32 "
        "{%0,%1,%2,%3}, {%4,%5,%6,%7}, {%8,%9}, {%0,%1,%2,%3};"
        : "+f"(d[0]), "+f"(d[1]), "+f"(d[2]), "+f"(d[3])
        : "r"(a[0]), "r"(a[1]), "r"(a[2]), "r"(a[3]), "r"(b0), "r"(b1));
}
__device__ __forceinline__ uint32_t pack_bf16x2(float lo, float hi) {
    __nv_bfloat162 h = __floats2bfloat162_rn(lo, hi);
    return *reinterpret_cast<uint32_t*>(&h);
}

// ---------------- kernel 0: probe target dtype layout ----------------
__global__ void rdl_probe(const int* __restrict__ t) {
    __shared__ int any;
    if (threadIdx.x == 0) any = 0;
    __syncthreads();
    int local = 0;
    for (int i = threadIdx.x; i < 2048; i += blockDim.x) local |= t[2 * i + 1];
    if (local) atomicOr(&any, 1);
    __syncthreads();
    if (threadIdx.x == 0) g_tgt64 = (any == 0) ? 1 : 0;
}

// ---------------- kernel 1: cross-entropy, warp-per-row ----------------
__global__ void rdl_ce(const float* __restrict__ pred, const void* __restrict__ tgt) {
    const int lane = threadIdx.x & 31, wid = threadIdx.x >> 5;
    const int row = blockIdx.x * 16 + wid;
    const float* p = pred + (size_t)row * C_CLS;

    float m = -3.4e38f;
    for (int c = lane; c < C_CLS; c += 32) m = fmaxf(m, p[c]);
#pragma unroll
    for (int o = 16; o; o >>= 1) m = fmaxf(m, __shfl_xor_sync(0xffffffffu, m, o));

    float s = 0.f;
    for (int c = lane; c < C_CLS; c += 32) s += expf(p[c] - m);
#pragma unroll
    for (int o = 16; o; o >>= 1) s += __shfl_xor_sync(0xffffffffu, s, o);

    if (lane == 0) {
        int t;
        if (g_tgt64) t = (int)((const long long*)tgt)[row];
        else         t = ((const int*)tgt)[row];
        t = min(max(t, 0), C_CLS - 1);
        g_ce[row] = -(p[t] - m - logf(s));
    }
}

// ---------------- kernel 2: norms + transposed normalized embeddings ----------------
__global__ void rdl_norm(const float* __restrict__ emb) {
    __shared__ float tile[32 * DD];
    __shared__ float rnorm[32];
    const int tid = threadIdx.x, lane = tid & 31, wid = tid >> 5;
    const int r0 = blockIdx.x * 32;

    for (int idx = tid; idx < 32 * DD; idx += 256)
        tile[idx] = emb[(size_t)r0 * DD + idx];
    __syncthreads();

#pragma unroll
    for (int q = 0; q < 4; q++) {
        const int rr = wid * 4 + q;
        float s = 0.f;
#pragma unroll
        for (int kk = lane; kk < DD; kk += 32) { float v = tile[rr * DD + kk]; s += v * v; }
#pragma unroll
        for (int o = 16; o; o >>= 1) s += __shfl_xor_sync(0xffffffffu, s, o);
        if (lane == 0) rnorm[rr] = rsqrtf(s);
    }
    __syncthreads();

    const int j = lane;
#pragma unroll
    for (int d8 = 0; d8 < 32; d8++) {
        const int d = d8 * 8 + wid;
        g_ehatT[(size_t)d * NN + r0 + j] = __float2bfloat16(tile[j * DD + d] * rnorm[j]);
    }
}

// ---------------- kernel 3: main fused kernel ----------------
__device__ __forceinline__ void issueA(int it, int tid, uint32_t sb,
                                       const float* __restrict__ adj,
                                       int row0, int kbase) {
    const uint32_t sa = sb + (uint32_t)((it % 3) * ASZ);
    const int kb = kbase + it * KC;
#pragma unroll
    for (int i = 0; i < 2; i++) {
        const int idx = tid + (i << 9);
        const int r = idx >> 3, c16 = idx & 7;
        cp16(sa + r * (A_STRIDE_F * 4) + c16 * 16,
             adj + (size_t)(row0 + r) * NN + (unsigned)(kb + c16 * 4));
    }
    cp_commit();
}
__device__ __forceinline__ void issueB(int it, int tid, uint32_t sb, int kbase) {
    const uint32_t sbb = sb + BOFF + (uint32_t)((it % 5) * BSZ);
    const int kb = kbase + it * KC;
#pragma unroll
    for (int i = 0; i < 2; i++) {
        const int idx = tid + (i << 9);
        const int r = idx >> 2, c16 = idx & 3;
        cp16(sbb + r * (P_STRIDE_H * 2) + c16 * 16,
             reinterpret_cast<const char*>(g_ehatT) +
                 ((size_t)r * NN + (unsigned)(kb + c16 * 8)) * 2);
    }
    cp_commit();
}

__global__ __launch_bounds__(THREADS, 1) void rdl_main(const float* __restrict__ adj) {
    extern __shared__ char smem[];
    const int tid = threadIdx.x, wid = tid >> 5, lane = tid & 31;
    const int rb = blockIdx.x & 63;
    const int ks = blockIdx.x >> 6;
    const int row0 = rb * MCTA;
    const int kbase = ks * KRANGE;
    const uint32_t sb = smem_u32(smem);

    const int mq = wid & 3;                  // M quadrant (32 rows)
    const int dq = wid >> 2;                 // D quadrant (64 cols)
    const int g = lane >> 2, c = lane & 3;

    const int lrow = lane & 15, lcol8 = (lane >> 4) << 3;
    const uint32_t a_base = sb + APOFF +
        (uint32_t)(((32 * mq + lrow) * P_STRIDE_H + lcol8) * 2);
    const uint32_t b_base0 = sb + BOFF +
        (uint32_t)(((64 * dq + lrow) * P_STRIDE_H + lcol8) * 2);

    // conversion indices: 2 float4 chunks per thread (rows match issueA mapping)
    const int cv_r0 = tid >> 3, cv_r1 = (tid + 512) >> 3;
    const int cv_c = tid & 7;

    float acc[2][8][4];
#pragma unroll
    for (int mi = 0; mi < 2; mi++)
#pragma unroll
        for (int ni = 0; ni < 8; ni++)
#pragma unroll
            for (int q = 0; q < 4; q++) acc[mi][ni][q] = 0.f;

    float abs_acc = 0.f, plain_acc = 0.f;

    // prologue: A0,A1, B0,B1,B2 ; convert A0 -> A'[0]
    issueA(0, tid, sb, adj, row0, kbase);
    issueA(1, tid, sb, adj, row0, kbase);
    issueB(0, tid, sb, kbase);
    issueB(1, tid, sb, kbase);
    issueB(2, tid, sb, kbase);
    asm volatile("cp.async.wait_group 4;" ::: "memory");
    __syncthreads();
    {
        const float* As = reinterpret_cast<const float*>(smem);  // stage 0
        char* Ap = smem + APOFF;                                  // A'[0]
        const float4 v0 = *reinterpret_cast<const float4*>(As + cv_r0 * A_STRIDE_F + cv_c * 4);
        const float4 v1 = *reinterpret_cast<const float4*>(As + cv_r1 * A_STRIDE_F + cv_c * 4);
        abs_acc   += fabsf(v0.x) + fabsf(v0.y) + fabsf(v0.z) + fabsf(v0.w)
                   + fabsf(v1.x) + fabsf(v1.y) + fabsf(v1.z) + fabsf(v1.w);
        plain_acc += (v0.x + v0.y) + (v0.z + v0.w) + (v1.x + v1.y) + (v1.z + v1.w);
        uint2 u0, u1;
        u0.x = pack_bf16x2(v0.x, v0.y); u0.y = pack_bf16x2(v0.z, v0.w);
        u1.x = pack_bf16x2(v1.x, v1.y); u1.y = pack_bf16x2(v1.z, v1.w);
        *reinterpret_cast<uint2*>(Ap + (cv_r0 * P_STRIDE_H + cv_c * 4) * 2) = u0;
        *reinterpret_cast<uint2*>(Ap + (cv_r1 * P_STRIDE_H + cv_c * 4) * 2) = u1;
    }

    // main loop: ONE barrier per iteration; convert(it+1) overlaps mma(it)
    for (int it = 0; it < NIT; ++it) {
        if (it + 2 < NIT) issueA(it + 2, tid, sb, adj, row0, kbase);
        if (it + 3 < NIT) issueB(it + 3, tid, sb, kbase);

        if (it < NIT - 3)       asm volatile("cp.async.wait_group 3;" ::: "memory");
        else if (it == NIT - 3) asm volatile("cp.async.wait_group 2;" ::: "memory");
        else                    asm volatile("cp.async.wait_group 0;" ::: "memory");
        __syncthreads();

        // convert A fp32 stage (it+1)%3 -> A'[(it+1)&1]  (+ fused exact sums)
        if (it + 1 < NIT) {
            const float* As = reinterpret_cast<const float*>(smem + ((it + 1) % 3) * ASZ);
            char* Ap = smem + APOFF + ((it + 1) & 1) * APSZ;
            const float4 v0 = *reinterpret_cast<const float4*>(As + cv_r0 * A_STRIDE_F + cv_c * 4);
            const float4 v1 = *reinterpret_cast<const float4*>(As + cv_r1 * A_STRIDE_F + cv_c * 4);
            abs_acc   += fabsf(v0.x) + fabsf(v0.y) + fabsf(v0.z) + fabsf(v0.w)
                       + fabsf(v1.x) + fabsf(v1.y) + fabsf(v1.z) + fabsf(v1.w);
            plain_acc += (v0.x + v0.y) + (v0.z + v0.w) + (v1.x + v1.y) + (v1.z + v1.w);
            uint2 u0, u1;
            u0.x = pack_bf16x2(v0.x, v0.y); u0.y = pack_bf16x2(v0.z, v0.w);
            u1.x = pack_bf16x2(v1.x, v1.y); u1.y = pack_bf16x2(v1.z, v1.w);
            *reinterpret_cast<uint2*>(Ap + (cv_r0 * P_STRIDE_H + cv_c * 4) * 2) = u0;
            *reinterpret_cast<uint2*>(Ap + (cv_r1 * P_STRIDE_H + cv_c * 4) * 2) = u1;
        }

        // mma on A'[it&1] and B[it%5]
        const uint32_t ab = a_base + (uint32_t)((it & 1) * APSZ);
        const uint32_t bb = b_base0 + (uint32_t)((it % 5) * BSZ);
#pragma unroll
        for (int kf = 0; kf < 2; kf++) {
            uint32_t bfr[4][4];
#pragma unroll
            for (int nip = 0; nip < 4; nip++)
                ldm_x4(bfr[nip], bb + (uint32_t)(((nip * 16) * P_STRIDE_H + kf * 16) * 2));
            uint32_t afr[2][4];
#pragma unroll
            for (int mi = 0; mi < 2; mi++)
                ldm_x4(afr[mi], ab + (uint32_t)(((mi * 16) * P_STRIDE_H + kf * 16) * 2));
#pragma unroll
            for (int mi = 0; mi < 2; mi++)
#pragma unroll
                for (int ni = 0; ni < 8; ni++)
                    mma_16816(acc[mi][ni], afr[mi],
                              bfr[ni >> 1][ni & 1], bfr[ni >> 1][(ni & 1) + 2]);
        }
    }

    // contraction: sem += out[m][d] * ehat[m][d]   (ehat[m][d] = g_ehatT[d][m])
    float sem_acc = 0.f;
#pragma unroll
    for (int mi = 0; mi < 2; mi++)
#pragma unroll
        for (int ni = 0; ni < 8; ni++) {
            const int m0 = row0 + 32 * mq + 16 * mi + g;
            const int d0 = 64 * dq + 8 * ni + 2 * c;
            const float e00 = __bfloat162float(g_ehatT[(size_t)d0 * NN + m0]);
            const float e01 = __bfloat162float(g_ehatT[(size_t)(d0 + 1) * NN + m0]);
            const float e10 = __bfloat162float(g_ehatT[(size_t)d0 * NN + m0 + 8]);
            const float e11 = __bfloat162float(g_ehatT[(size_t)(d0 + 1) * NN + m0 + 8]);
            sem_acc += acc[mi][ni][0] * e00 + acc[mi][ni][1] * e01
                     + acc[mi][ni][2] * e10 + acc[mi][ni][3] * e11;
        }

    // block reduce sem/abs/plain
#pragma unroll
    for (int o = 16; o; o >>= 1) {
        sem_acc   += __shfl_xor_sync(0xffffffffu, sem_acc, o);
        abs_acc   += __shfl_xor_sync(0xffffffffu, abs_acc, o);
        plain_acc += __shfl_xor_sync(0xffffffffu, plain_acc, o);
    }
    float* red = reinterpret_cast<float*>(smem);
    __syncthreads();
    if (lane == 0) { red[wid] = sem_acc; red[16 + wid] = abs_acc; red[32 + wid] = plain_acc; }
    __syncthreads();
    if (tid == 0) {
        float s2 = 0.f, a2 = 0.f, p2 = 0.f;
#pragma unroll
        for (int w = 0; w < 16; w++) { s2 += red[w]; a2 += red[16 + w]; p2 += red[32 + w]; }
        g_psem[blockIdx.x] = s2; g_pabs[blockIdx.x] = a2; g_pplain[blockIdx.x] = p2;
    }
}

// ---------------- kernel 4: combine ----------------
__global__ void rdl_combine(float* __restrict__ out) {
    const int tid = threadIdx.x, lane = tid & 31, wid = tid >> 5;
    __shared__ float red[4][8];
    float ce = 0.f, sem = 0.f, ab = 0.f, pl = 0.f;
    for (int i = tid; i < B_ROWS; i += 256) ce += g_ce[i];
    for (int i = tid; i < NCTA; i += 256) { sem += g_psem[i]; ab += g_pabs[i]; pl += g_pplain[i]; }
#pragma unroll
    for (int o = 16; o; o >>= 1) {
        ce  += __shfl_xor_sync(0xffffffffu, ce, o);
        sem += __shfl_xor_sync(0xffffffffu, sem, o);
        ab  += __shfl_xor_sync(0xffffffffu, ab, o);
        pl  += __shfl_xor_sync(0xffffffffu, pl, o);
    }
    if (lane == 0) { red[0][wid] = ce; red[1][wid] = sem; red[2][wid] = ab; red[3][wid] = pl; }
    __syncthreads();
    if (tid == 0) {
        float tce = 0.f, tsem = 0.f, tab = 0.f, tpl = 0.f;
#pragma unroll
        for (int w = 0; w < 8; w++) {
            tce += red[0][w]; tsem += red[1][w]; tab += red[2][w]; tpl += red[3][w];
        }
        const float invB  = 1.0f / (float)B_ROWS;
        const float invN2 = 1.0f / ((float)NN * (float)NN);
        const float l_task   = tce * invB;
        const float l_sparse = tab * invN2;
        const float l_sem    = (tpl - tsem) * invN2;
        out[0] = 1.0f * l_task + 0.01f * l_sparse + 0.1f * l_sem;
    }
}

// ---------------- launch ----------------
extern "C" void kernel_launch(void* const* d_in, const int* in_sizes, int n_in,
                              void* d_out, int out_size) {
    const float* pred = nullptr; const void* tgt = nullptr;
    const float* adj  = nullptr; const float* emb = nullptr;
    for (int i = 0; i < n_in; i++) {
        switch (in_sizes[i]) {
            case B_ROWS * C_CLS:     pred = (const float*)d_in[i]; break;
            case B_ROWS:             tgt  = d_in[i];               break;
            case NN * NN:            adj  = (const float*)d_in[i]; break;
            case NN * DD:            emb  = (const float*)d_in[i]; break;
            default: break;
        }
    }
    float* out = (float*)d_out;
    (void)out_size;

    rdl_probe<<<1, 1024>>>((const int*)tgt);
    rdl_ce<<<B_ROWS / 16, 512>>>(pred, tgt);
    rdl_norm<<<NN / 32, 256>>>(emb);
    cudaFuncSetAttribute(rdl_main, cudaFuncAttributeMaxDynamicSharedMemorySize, SMEM_BYTES);
    rdl_main<<<NCTA, THREADS, SMEM_BYTES>>>(adj);
    rdl_combine<<<1, 256>>>(out);
}

// round 11
// speedup vs baseline: 1.0618x; 1.0618x over previous
#include <cuda_runtime.h>
#include <cuda_bf16.h>
#include <cstdint>

// ---------------- problem constants ----------------
#define B_ROWS 4096
#define C_CLS  1000
#define NN     8192
#define DD     256

// main kernel tiling: CTA = M128 x D128, warp tile 64x32 (8 warps, 2x4)
#define MCTA    128
#define DCTA    128
#define KSPLIT  2
#define KC      32
#define KRANGE  (NN / KSPLIT)       // 4096
#define NIT     (KRANGE / KC)       // 128
#define NCTA    256                 // 64 Mblk x 2 Dblk x 2 Kblk
#define THREADS 256

// smem: A' bf16 [128][40] x2, B bf16 [128][40] x3
#define P_STRIDE_H 40
#define APSZ  (MCTA * P_STRIDE_H * 2)     // 10240
#define BSZ   (DCTA * P_STRIDE_H * 2)     // 10240
#define BOFF  (2 * APSZ)                  // 20480
#define SMEM_BYTES (2 * APSZ + 3 * BSZ)   // 51200

// ---------------- device scratch ----------------
__device__ __nv_bfloat16 g_ehatT[(size_t)DD * NN];  // Ê^T [256][8192] bf16
__device__ float g_ce[B_ROWS];
__device__ float g_psem[NCTA];
__device__ float g_pabs[NCTA];
__device__ float g_pplain[NCTA];
__device__ int   g_tgt64;

// ---------------- helpers ----------------
__device__ __forceinline__ uint32_t smem_u32(const void* p) {
    uint32_t a;
    asm("{ .reg .u64 t; cvta.to.shared.u64 t, %1; cvt.u32.u64 %0, t; }" : "=r"(a) : "l"(p));
    return a;
}
__device__ __forceinline__ void cp16(uint32_t s, const void* g) {
    asm volatile("cp.async.cg.shared.global [%0], [%1], 16;" :: "r"(s), "l"(g));
}
__device__ __forceinline__ void cp_commit() {
    asm volatile("cp.async.commit_group;" ::: "memory");
}
__device__ __forceinline__ void ldm_x4(uint32_t* r, uint32_t addr) {
    asm volatile("ldmatrix.sync.aligned.m8n8.x4.shared.b16 {%0,%1,%2,%3}, [%4];"
                 : "=r"(r[0]), "=r"(r[1]), "=r"(r[2]), "=r"(r[3]) : "r"(addr));
}
__device__ __forceinline__ void mma_16816(float* d, const uint32_t* a,
                                          uint32_t b0, uint32_t b1) {
    asm volatile(
        "mma.sync.aligned.m16n8k16.row.col.f32.bf16.bf16.f32 "
        "{%0,%1,%2,%3}, {%4,%5,%6,%7}, {%8,%9}, {%0,%1,%2,%3};"
        : "+f"(d[0]), "+f"(d[1]), "+f"(d[2]), "+f"(d[3])
        : "r"(a[0]), "r"(a[1]), "r"(a[2]), "r"(a[3]), "r"(b0), "r"(b1));
}
__device__ __forceinline__ uint32_t pack_bf16x2(float lo, float hi) {
    __nv_bfloat162 h = __floats2bfloat162_rn(lo, hi);
    return *reinterpret_cast<uint32_t*>(&h);
}

// ---------------- kernel 0: probe target dtype layout ----------------
__global__ void rdl_probe(const int* __restrict__ t) {
    __shared__ int any;
    if (threadIdx.x == 0) any = 0;
    __syncthreads();
    int local = 0;
    for (int i = threadIdx.x; i < 2048; i += blockDim.x) local |= t[2 * i + 1];
    if (local) atomicOr(&any, 1);
    __syncthreads();
    if (threadIdx.x == 0) g_tgt64 = (any == 0) ? 1 : 0;
}

// ---------------- kernel 1: cross-entropy, warp-per-row ----------------
__global__ void rdl_ce(const float* __restrict__ pred, const void* __restrict__ tgt) {
    const int lane = threadIdx.x & 31, wid = threadIdx.x >> 5;
    const int row = blockIdx.x * 16 + wid;
    const float* p = pred + (size_t)row * C_CLS;

    float m = -3.4e38f;
    for (int c = lane; c < C_CLS; c += 32) m = fmaxf(m, p[c]);
#pragma unroll
    for (int o = 16; o; o >>= 1) m = fmaxf(m, __shfl_xor_sync(0xffffffffu, m, o));

    float s = 0.f;
    for (int c = lane; c < C_CLS; c += 32) s += expf(p[c] - m);
#pragma unroll
    for (int o = 16; o; o >>= 1) s += __shfl_xor_sync(0xffffffffu, s, o);

    if (lane == 0) {
        int t;
        if (g_tgt64) t = (int)((const long long*)tgt)[row];
        else         t = ((const int*)tgt)[row];
        t = min(max(t, 0), C_CLS - 1);
        g_ce[row] = -(p[t] - m - logf(s));
    }
}

// ---------------- kernel 2: norms + transposed normalized embeddings ----------------
__global__ void rdl_norm(const float* __restrict__ emb) {
    __shared__ float tile[32 * DD];
    __shared__ float rnorm[32];
    const int tid = threadIdx.x, lane = tid & 31, wid = tid >> 5;
    const int r0 = blockIdx.x * 32;

    for (int idx = tid; idx < 32 * DD; idx += 256)
        tile[idx] = emb[(size_t)r0 * DD + idx];
    __syncthreads();

#pragma unroll
    for (int q = 0; q < 4; q++) {
        const int rr = wid * 4 + q;
        float s = 0.f;
#pragma unroll
        for (int kk = lane; kk < DD; kk += 32) { float v = tile[rr * DD + kk]; s += v * v; }
#pragma unroll
        for (int o = 16; o; o >>= 1) s += __shfl_xor_sync(0xffffffffu, s, o);
        if (lane == 0) rnorm[rr] = rsqrtf(s);
    }
    __syncthreads();

    const int j = lane;
#pragma unroll
    for (int d8 = 0; d8 < 32; d8++) {
        const int d = d8 * 8 + wid;
        g_ehatT[(size_t)d * NN + r0 + j] = __float2bfloat16(tile[j * DD + d] * rnorm[j]);
    }
}

// ---------------- kernel 3: main fused kernel ----------------
__device__ __forceinline__ void issueB(int it, int tid, uint32_t sb, int d0, int kbase) {
    const uint32_t sbb = sb + BOFF + (uint32_t)((it % 3) * BSZ);
    const int kb = kbase + it * KC;
#pragma unroll
    for (int i = 0; i < 2; i++) {
        const int idx = tid + (i << 8);
        const int r = idx >> 2, c = idx & 3;
        cp16(sbb + r * (P_STRIDE_H * 2) + c * 16,
             reinterpret_cast<const char*>(g_ehatT) +
                 ((size_t)(d0 + r) * NN + (unsigned)(kb + c * 8)) * 2);
    }
    cp_commit();
}

__global__ __launch_bounds__(THREADS, 2) void rdl_main(const float* __restrict__ adj) {
    extern __shared__ char smem[];
    const int tid = threadIdx.x, wid = tid >> 5, lane = tid & 31;
    const int rb = blockIdx.x & 63;
    const int db = (blockIdx.x >> 6) & 1;
    const int ks = blockIdx.x >> 7;
    const int row0 = rb * MCTA;
    const int d0base = db * DCTA;
    const int kbase = ks * KRANGE;
    const uint32_t sb = smem_u32(smem);

    const int mq = wid & 1;                  // M half (64 rows)
    const int dq = wid >> 1;                 // D quarter (32 cols)
    const int g = lane >> 2, c = lane & 3;

    const int lrow = lane & 15, lcol8 = (lane >> 4) << 3;
    const uint32_t a_base = sb + (uint32_t)(((64 * mq + lrow) * P_STRIDE_H + lcol8) * 2);
    const uint32_t b_base0 = sb + BOFF + (uint32_t)(((32 * dq + lrow) * P_STRIDE_H + lcol8) * 2);

    // A LDG/STS mapping: 4 float4 per thread, rows cv_r+32i, cols cv_c*4
    const int cv_r = tid >> 3, cv_c = tid & 7;
    const float4* ap = reinterpret_cast<const float4*>(
        adj + (size_t)(row0 + cv_r) * NN + (unsigned)kbase) + cv_c;
    const uint32_t ap_off = (uint32_t)((cv_r * P_STRIDE_H + cv_c * 4) * 2);  // byte offset

    float acc[4][4][4];
#pragma unroll
    for (int mi = 0; mi < 4; mi++)
#pragma unroll
        for (int ni = 0; ni < 4; ni++)
#pragma unroll
            for (int q = 0; q < 4; q++) acc[mi][ni][q] = 0.f;

    float abs_acc = 0.f, plain_acc = 0.f;
    float4 rv[4];

    // prologue: B(0), B(1); LDG+convert A'(0)
    issueB(0, tid, sb, d0base, kbase);
    issueB(1, tid, sb, d0base, kbase);
#pragma unroll
    for (int i = 0; i < 4; i++) rv[i] = ap[(size_t)i * 8 * NN];
#pragma unroll
    for (int i = 0; i < 4; i++) {
        const float4 v = rv[i];
        if (db == 0) {
            abs_acc   += fabsf(v.x) + fabsf(v.y) + fabsf(v.z) + fabsf(v.w);
            plain_acc += (v.x + v.y) + (v.z + v.w);
        }
        uint2 u; u.x = pack_bf16x2(v.x, v.y); u.y = pack_bf16x2(v.z, v.w);
        *reinterpret_cast<uint2*>(smem + ap_off + (uint32_t)(i * 32 * P_STRIDE_H * 2)) = u;
    }
    // prefetch A(1)
#pragma unroll
    for (int i = 0; i < 4; i++) rv[i] = ap[(size_t)i * 8 * NN + 8];

    for (int it = 0; it < NIT; ++it) {
        if (it + 1 < NIT) asm volatile("cp.async.wait_group 1;" ::: "memory");
        else              asm volatile("cp.async.wait_group 0;" ::: "memory");
        __syncthreads();

        if (it + 2 < NIT) issueB(it + 2, tid, sb, d0base, kbase);

        // convert A(it+1) regs -> A'[(it+1)&1]; fused exact sums (db==0 only)
        if (it + 1 < NIT) {
            char* Ap = smem + ((it + 1) & 1) * APSZ;
#pragma unroll
            for (int i = 0; i < 4; i++) {
                const float4 v = rv[i];
                if (db == 0) {
                    abs_acc   += fabsf(v.x) + fabsf(v.y) + fabsf(v.z) + fabsf(v.w);
                    plain_acc += (v.x + v.y) + (v.z + v.w);
                }
                uint2 u; u.x = pack_bf16x2(v.x, v.y); u.y = pack_bf16x2(v.z, v.w);
                *reinterpret_cast<uint2*>(Ap + ap_off + (uint32_t)(i * 32 * P_STRIDE_H * 2)) = u;
            }
        }
        // prefetch A(it+2)
        if (it + 2 < NIT) {
            const size_t ko = (size_t)(it + 2) * (KC / 4);
#pragma unroll
            for (int i = 0; i < 4; i++) rv[i] = ap[(size_t)i * 8 * NN + ko];
        }

        // mma on A'[it&1], B[it%3]
        const uint32_t ab = a_base + (uint32_t)((it & 1) * APSZ);
        const uint32_t bb = b_base0 + (uint32_t)((it % 3) * BSZ);
#pragma unroll
        for (int kf = 0; kf < 2; kf++) {
            uint32_t bfr[2][4];
#pragma unroll
            for (int pr = 0; pr < 2; pr++)
                ldm_x4(bfr[pr], bb + (uint32_t)(((pr * 16) * P_STRIDE_H + kf * 16) * 2));
            uint32_t afr[4][4];
#pragma unroll
            for (int mi = 0; mi < 4; mi++)
                ldm_x4(afr[mi], ab + (uint32_t)(((mi * 16) * P_STRIDE_H + kf * 16) * 2));
#pragma unroll
            for (int mi = 0; mi < 4; mi++)
#pragma unroll
                for (int ni = 0; ni < 4; ni++)
                    mma_16816(acc[mi][ni], afr[mi],
                              bfr[ni >> 1][ni & 1], bfr[ni >> 1][(ni & 1) + 2]);
        }
    }

    // contraction: sem += out[m][d] * ehat[m][d]   (ehat[m][d] = g_ehatT[d][m])
    float sem_acc = 0.f;
#pragma unroll
    for (int mi = 0; mi < 4; mi++)
#pragma unroll
        for (int ni = 0; ni < 4; ni++) {
            const int m0 = row0 + 64 * mq + 16 * mi + g;
            const int d0 = d0base + 32 * dq + 8 * ni + 2 * c;
            const float e00 = __bfloat162float(g_ehatT[(size_t)d0 * NN + m0]);
            const float e01 = __bfloat162float(g_ehatT[(size_t)(d0 + 1) * NN + m0]);
            const float e10 = __bfloat162float(g_ehatT[(size_t)d0 * NN + m0 + 8]);
            const float e11 = __bfloat162float(g_ehatT[(size_t)(d0 + 1) * NN + m0 + 8]);
            sem_acc += acc[mi][ni][0] * e00 + acc[mi][ni][1] * e01
                     + acc[mi][ni][2] * e10 + acc[mi][ni][3] * e11;
        }

    // block reduce sem/abs/plain
#pragma unroll
    for (int o = 16; o; o >>= 1) {
        sem_acc   += __shfl_xor_sync(0xffffffffu, sem_acc, o);
        abs_acc   += __shfl_xor_sync(0xffffffffu, abs_acc, o);
        plain_acc += __shfl_xor_sync(0xffffffffu, plain_acc, o);
    }
    float* red = reinterpret_cast<float*>(smem);
    __syncthreads();
    if (lane == 0) { red[wid] = sem_acc; red[8 + wid] = abs_acc; red[16 + wid] = plain_acc; }
    __syncthreads();
    if (tid == 0) {
        float s2 = 0.f, a2 = 0.f, p2 = 0.f;
#pragma unroll
        for (int w = 0; w < 8; w++) { s2 += red[w]; a2 += red[8 + w]; p2 += red[16 + w]; }
        g_psem[blockIdx.x] = s2; g_pabs[blockIdx.x] = a2; g_pplain[blockIdx.x] = p2;
    }
}

// ---------------- kernel 4: combine ----------------
__global__ void rdl_combine(float* __restrict__ out) {
    const int tid = threadIdx.x, lane = tid & 31, wid = tid >> 5;
    __shared__ float red[4][8];
    float ce = 0.f, sem = 0.f, ab = 0.f, pl = 0.f;
    for (int i = tid; i < B_ROWS; i += 256) ce += g_ce[i];
    for (int i = tid; i < NCTA; i += 256) { sem += g_psem[i]; ab += g_pabs[i]; pl += g_pplain[i]; }
#pragma unroll
    for (int o = 16; o; o >>= 1) {
        ce  += __shfl_xor_sync(0xffffffffu, ce, o);
        sem += __shfl_xor_sync(0xffffffffu, sem, o);
        ab  += __shfl_xor_sync(0xffffffffu, ab, o);
        pl  += __shfl_xor_sync(0xffffffffu, pl, o);
    }
    if (lane == 0) { red[0][wid] = ce; red[1][wid] = sem; red[2][wid] = ab; red[3][wid] = pl; }
    __syncthreads();
    if (tid == 0) {
        float tce = 0.f, tsem = 0.f, tab = 0.f, tpl = 0.f;
#pragma unroll
        for (int w = 0; w < 8; w++) {
            tce += red[0][w]; tsem += red[1][w]; tab += red[2][w]; tpl += red[3][w];
        }
        const float invB  = 1.0f / (float)B_ROWS;
        const float invN2 = 1.0f / ((float)NN * (float)NN);
        const float l_task   = tce * invB;
        const float l_sparse = tab * invN2;
        const float l_sem    = (tpl - tsem) * invN2;
        out[0] = 1.0f * l_task + 0.01f * l_sparse + 0.1f * l_sem;
    }
}

// ---------------- launch ----------------
extern "C" void kernel_launch(void* const* d_in, const int* in_sizes, int n_in,
                              void* d_out, int out_size) {
    const float* pred = nullptr; const void* tgt = nullptr;
    const float* adj  = nullptr; const float* emb = nullptr;
    for (int i = 0; i < n_in; i++) {
        switch (in_sizes[i]) {
            case B_ROWS * C_CLS:     pred = (const float*)d_in[i]; break;
            case B_ROWS:             tgt  = d_in[i];               break;
            case NN * NN:            adj  = (const float*)d_in[i]; break;
            case NN * DD:            emb  = (const float*)d_in[i]; break;
            default: break;
        }
    }
    float* out = (float*)d_out;
    (void)out_size;

    rdl_probe<<<1, 1024>>>((const int*)tgt);
    rdl_ce<<<B_ROWS / 16, 512>>>(pred, tgt);
    rdl_norm<<<NN / 32, 256>>>(emb);
    cudaFuncSetAttribute(rdl_main, cudaFuncAttributeMaxDynamicSharedMemorySize, SMEM_BYTES);
    rdl_main<<<NCTA, THREADS, SMEM_BYTES>>>(adj);
    rdl_combine<<<1, 256>>>(out);
}

// round 12
// speedup vs baseline: 1.0981x; 1.0342x over previous
#include <cuda_runtime.h>
#include <cuda_bf16.h>
#include <cstdint>

// ---------------- problem constants ----------------
#define B_ROWS 4096
#define C_CLS  1000
#define NN     8192
#define DD     256

// main kernel tiling: tile = M128 x D128 x K2048; 64*2*4 = 512 tiles
#define MCTA    128
#define DCTA    128
#define KSPLIT  4
#define KC      32
#define KRANGE  (NN / KSPLIT)       // 2048
#define NIT     (KRANGE / KC)       // 64
#define TILES   512
#define PCTA    296                 // 2 CTAs x 148 SMs, persistent
#define THREADS 256

// smem: A' bf16 [128][40] x2, B bf16 [128][40] x3, red region
#define P_STRIDE_H 40
#define APSZ  (MCTA * P_STRIDE_H * 2)     // 10240
#define BSZ   (DCTA * P_STRIDE_H * 2)     // 10240
#define BOFF  (2 * APSZ)                  // 20480
#define REDOFF (2 * APSZ + 3 * BSZ)       // 51200
#define SMEM_BYTES (REDOFF + 128)         // 51328

// ---------------- device scratch ----------------
__device__ __nv_bfloat16 g_ehatT[(size_t)DD * NN];  // Ê^T [256][8192] bf16
__device__ float g_ce[B_ROWS];
__device__ float g_psem[TILES];
__device__ float g_pabs[TILES];
__device__ float g_pplain[TILES];
__device__ int   g_tgt64;
__device__ int   g_tile;            // dynamic tile queue head

// ---------------- helpers ----------------
__device__ __forceinline__ uint32_t smem_u32(const void* p) {
    uint32_t a;
    asm("{ .reg .u64 t; cvta.to.shared.u64 t, %1; cvt.u32.u64 %0, t; }" : "=r"(a) : "l"(p));
    return a;
}
__device__ __forceinline__ void cp16(uint32_t s, const void* g) {
    asm volatile("cp.async.cg.shared.global [%0], [%1], 16;" :: "r"(s), "l"(g));
}
__device__ __forceinline__ void cp_commit() {
    asm volatile("cp.async.commit_group;" ::: "memory");
}
__device__ __forceinline__ void ldm_x4(uint32_t* r, uint32_t addr) {
    asm volatile("ldmatrix.sync.aligned.m8n8.x4.shared.b16 {%0,%1,%2,%3}, [%4];"
                 : "=r"(r[0]), "=r"(r[1]), "=r"(r[2]), "=r"(r[3]) : "r"(addr));
}
__device__ __forceinline__ void mma_16816(float* d, const uint32_t* a,
                                          uint32_t b0, uint32_t b1) {
    asm volatile(
        "mma.sync.aligned.m16n8k16.row.col.f32.bf16.bf16.f32 "
        "{%0,%1,%2,%3}, {%4,%5,%6,%7}, {%8,%9}, {%0,%1,%2,%3};"
        : "+f"(d[0]), "+f"(d[1]), "+f"(d[2]), "+f"(d[3])
        : "r"(a[0]), "r"(a[1]), "r"(a[2]), "r"(a[3]), "r"(b0), "r"(b1));
}
__device__ __forceinline__ uint32_t pack_bf16x2(float lo, float hi) {
    __nv_bfloat162 h = __floats2bfloat162_rn(lo, hi);
    return *reinterpret_cast<uint32_t*>(&h);
}

// ---------------- kernel 0: probe target dtype + reset queue ----------------
__global__ void rdl_probe(const int* __restrict__ t) {
    __shared__ int any;
    if (threadIdx.x == 0) { any = 0; g_tile = 0; }
    __syncthreads();
    int local = 0;
    for (int i = threadIdx.x; i < 2048; i += blockDim.x) local |= t[2 * i + 1];
    if (local) atomicOr(&any, 1);
    __syncthreads();
    if (threadIdx.x == 0) g_tgt64 = (any == 0) ? 1 : 0;
}

// ---------------- kernel 1: cross-entropy, warp-per-row ----------------
__global__ void rdl_ce(const float* __restrict__ pred, const void* __restrict__ tgt) {
    const int lane = threadIdx.x & 31, wid = threadIdx.x >> 5;
    const int row = blockIdx.x * 16 + wid;
    const float* p = pred + (size_t)row * C_CLS;

    float m = -3.4e38f;
    for (int c = lane; c < C_CLS; c += 32) m = fmaxf(m, p[c]);
#pragma unroll
    for (int o = 16; o; o >>= 1) m = fmaxf(m, __shfl_xor_sync(0xffffffffu, m, o));

    float s = 0.f;
    for (int c = lane; c < C_CLS; c += 32) s += expf(p[c] - m);
#pragma unroll
    for (int o = 16; o; o >>= 1) s += __shfl_xor_sync(0xffffffffu, s, o);

    if (lane == 0) {
        int t;
        if (g_tgt64) t = (int)((const long long*)tgt)[row];
        else         t = ((const int*)tgt)[row];
        t = min(max(t, 0), C_CLS - 1);
        g_ce[row] = -(p[t] - m - logf(s));
    }
}

// ---------------- kernel 2: norms + transposed normalized embeddings ----------------
__global__ void rdl_norm(const float* __restrict__ emb) {
    __shared__ float tile[32 * DD];
    __shared__ float rnorm[32];
    const int tid = threadIdx.x, lane = tid & 31, wid = tid >> 5;
    const int r0 = blockIdx.x * 32;

    for (int idx = tid; idx < 32 * DD; idx += 256)
        tile[idx] = emb[(size_t)r0 * DD + idx];
    __syncthreads();

#pragma unroll
    for (int q = 0; q < 4; q++) {
        const int rr = wid * 4 + q;
        float s = 0.f;
#pragma unroll
        for (int kk = lane; kk < DD; kk += 32) { float v = tile[rr * DD + kk]; s += v * v; }
#pragma unroll
        for (int o = 16; o; o >>= 1) s += __shfl_xor_sync(0xffffffffu, s, o);
        if (lane == 0) rnorm[rr] = rsqrtf(s);
    }
    __syncthreads();

    const int j = lane;
#pragma unroll
    for (int d8 = 0; d8 < 32; d8++) {
        const int d = d8 * 8 + wid;
        g_ehatT[(size_t)d * NN + r0 + j] = __float2bfloat16(tile[j * DD + d] * rnorm[j]);
    }
}

// ---------------- kernel 3: persistent fused main kernel ----------------
__device__ __forceinline__ void issueB(int it, int tid, uint32_t sb, int d0, int kbase) {
    const uint32_t sbb = sb + BOFF + (uint32_t)((it % 3) * BSZ);
    const int kb = kbase + it * KC;
#pragma unroll
    for (int i = 0; i < 2; i++) {
        const int idx = tid + (i << 8);
        const int r = idx >> 2, c = idx & 3;
        cp16(sbb + r * (P_STRIDE_H * 2) + c * 16,
             reinterpret_cast<const char*>(g_ehatT) +
                 ((size_t)(d0 + r) * NN + (unsigned)(kb + c * 8)) * 2);
    }
    cp_commit();
}

__global__ __launch_bounds__(THREADS, 2) void rdl_main(const float* __restrict__ adj) {
    extern __shared__ char smem[];
    const int tid = threadIdx.x, wid = tid >> 5, lane = tid & 31;
    const uint32_t sb = smem_u32(smem);

    const int mq = wid & 1;                  // M half (64 rows)
    const int dq = wid >> 1;                 // D quarter (32 cols)
    const int g = lane >> 2, c = lane & 3;

    const int lrow = lane & 15, lcol8 = (lane >> 4) << 3;
    const uint32_t a_base = sb + (uint32_t)(((64 * mq + lrow) * P_STRIDE_H + lcol8) * 2);
    const uint32_t b_base0 = sb + BOFF + (uint32_t)(((32 * dq + lrow) * P_STRIDE_H + lcol8) * 2);

    const int cv_r = tid >> 3, cv_c = tid & 7;
    const uint32_t ap_off = (uint32_t)((cv_r * P_STRIDE_H + cv_c * 4) * 2);

    int* tile_sh = reinterpret_cast<int*>(smem + REDOFF + 96);
    float* red = reinterpret_cast<float*>(smem + REDOFF);

    for (;;) {
        if (tid == 0) *tile_sh = atomicAdd(&g_tile, 1);
        __syncthreads();
        const int t = *tile_sh;
        __syncthreads();          // tile_sh stable before next overwrite
        if (t >= TILES) break;

        const int row0   = (t & 63) * MCTA;
        const int db     = (t >> 6) & 1;
        const int d0base = db * DCTA;
        const int kbase  = (t >> 7) * KRANGE;

        const float4* ap = reinterpret_cast<const float4*>(
            adj + (size_t)(row0 + cv_r) * NN + (unsigned)kbase) + cv_c;

        float acc[4][4][4];
#pragma unroll
        for (int mi = 0; mi < 4; mi++)
#pragma unroll
            for (int ni = 0; ni < 4; ni++)
#pragma unroll
                for (int q = 0; q < 4; q++) acc[mi][ni][q] = 0.f;

        float abs_acc = 0.f, plain_acc = 0.f;
        float4 rv[4];

        // prologue: B(0), B(1); LDG+convert A'(0); prefetch A(1)
        issueB(0, tid, sb, d0base, kbase);
        issueB(1, tid, sb, d0base, kbase);
#pragma unroll
        for (int i = 0; i < 4; i++) rv[i] = ap[(size_t)i * 8 * NN];
#pragma unroll
        for (int i = 0; i < 4; i++) {
            const float4 v = rv[i];
            if (db == 0) {
                abs_acc   += fabsf(v.x) + fabsf(v.y) + fabsf(v.z) + fabsf(v.w);
                plain_acc += (v.x + v.y) + (v.z + v.w);
            }
            uint2 u; u.x = pack_bf16x2(v.x, v.y); u.y = pack_bf16x2(v.z, v.w);
            *reinterpret_cast<uint2*>(smem + ap_off + (uint32_t)(i * 32 * P_STRIDE_H * 2)) = u;
        }
#pragma unroll
        for (int i = 0; i < 4; i++) rv[i] = ap[(size_t)i * 8 * NN + 8];

        for (int it = 0; it < NIT; ++it) {
            if (it + 1 < NIT) asm volatile("cp.async.wait_group 1;" ::: "memory");
            else              asm volatile("cp.async.wait_group 0;" ::: "memory");
            __syncthreads();

            if (it + 2 < NIT) issueB(it + 2, tid, sb, d0base, kbase);

            // convert A(it+1) regs -> A'[(it+1)&1]; fused exact sums (db==0 only)
            if (it + 1 < NIT) {
                char* Ap = smem + ((it + 1) & 1) * APSZ;
#pragma unroll
                for (int i = 0; i < 4; i++) {
                    const float4 v = rv[i];
                    if (db == 0) {
                        abs_acc   += fabsf(v.x) + fabsf(v.y) + fabsf(v.z) + fabsf(v.w);
                        plain_acc += (v.x + v.y) + (v.z + v.w);
                    }
                    uint2 u; u.x = pack_bf16x2(v.x, v.y); u.y = pack_bf16x2(v.z, v.w);
                    *reinterpret_cast<uint2*>(Ap + ap_off + (uint32_t)(i * 32 * P_STRIDE_H * 2)) = u;
                }
            }
            // prefetch A(it+2)
            if (it + 2 < NIT) {
                const size_t ko = (size_t)(it + 2) * (KC / 4);
#pragma unroll
                for (int i = 0; i < 4; i++) rv[i] = ap[(size_t)i * 8 * NN + ko];
            }

            // mma on A'[it&1], B[it%3]
            const uint32_t ab = a_base + (uint32_t)((it & 1) * APSZ);
            const uint32_t bb = b_base0 + (uint32_t)((it % 3) * BSZ);
#pragma unroll
            for (int kf = 0; kf < 2; kf++) {
                uint32_t bfr[2][4];
#pragma unroll
                for (int pr = 0; pr < 2; pr++)
                    ldm_x4(bfr[pr], bb + (uint32_t)(((pr * 16) * P_STRIDE_H + kf * 16) * 2));
                uint32_t afr[4][4];
#pragma unroll
                for (int mi = 0; mi < 4; mi++)
                    ldm_x4(afr[mi], ab + (uint32_t)(((mi * 16) * P_STRIDE_H + kf * 16) * 2));
#pragma unroll
                for (int mi = 0; mi < 4; mi++)
#pragma unroll
                    for (int ni = 0; ni < 4; ni++)
                        mma_16816(acc[mi][ni], afr[mi],
                                  bfr[ni >> 1][ni & 1], bfr[ni >> 1][(ni & 1) + 2]);
            }
        }

        // per-tile epilogue: sem contraction + reduce + store (keyed by tile -> deterministic)
        float sem_acc = 0.f;
#pragma unroll
        for (int mi = 0; mi < 4; mi++)
#pragma unroll
            for (int ni = 0; ni < 4; ni++) {
                const int m0 = row0 + 64 * mq + 16 * mi + g;
                const int d0 = d0base + 32 * dq + 8 * ni + 2 * c;
                const float e00 = __bfloat162float(g_ehatT[(size_t)d0 * NN + m0]);
                const float e01 = __bfloat162float(g_ehatT[(size_t)(d0 + 1) * NN + m0]);
                const float e10 = __bfloat162float(g_ehatT[(size_t)d0 * NN + m0 + 8]);
                const float e11 = __bfloat162float(g_ehatT[(size_t)(d0 + 1) * NN + m0 + 8]);
                sem_acc += acc[mi][ni][0] * e00 + acc[mi][ni][1] * e01
                         + acc[mi][ni][2] * e10 + acc[mi][ni][3] * e11;
            }
#pragma unroll
        for (int o = 16; o; o >>= 1) {
            sem_acc   += __shfl_xor_sync(0xffffffffu, sem_acc, o);
            abs_acc   += __shfl_xor_sync(0xffffffffu, abs_acc, o);
            plain_acc += __shfl_xor_sync(0xffffffffu, plain_acc, o);
        }
        __syncthreads();   // all warps past smem reads of this tile
        if (lane == 0) { red[wid] = sem_acc; red[8 + wid] = abs_acc; red[16 + wid] = plain_acc; }
        __syncthreads();
        if (tid == 0) {
            float s2 = 0.f, a2 = 0.f, p2 = 0.f;
#pragma unroll
            for (int w = 0; w < 8; w++) { s2 += red[w]; a2 += red[8 + w]; p2 += red[16 + w]; }
            g_psem[t] = s2; g_pabs[t] = a2; g_pplain[t] = p2;
        }
        __syncthreads();
    }
}

// ---------------- kernel 4: combine ----------------
__global__ void rdl_combine(float* __restrict__ out) {
    const int tid = threadIdx.x, lane = tid & 31, wid = tid >> 5;
    __shared__ float red[4][8];
    float ce = 0.f, sem = 0.f, ab = 0.f, pl = 0.f;
    for (int i = tid; i < B_ROWS; i += 256) ce += g_ce[i];
    for (int i = tid; i < TILES; i += 256) { sem += g_psem[i]; ab += g_pabs[i]; pl += g_pplain[i]; }
#pragma unroll
    for (int o = 16; o; o >>= 1) {
        ce  += __shfl_xor_sync(0xffffffffu, ce, o);
        sem += __shfl_xor_sync(0xffffffffu, sem, o);
        ab  += __shfl_xor_sync(0xffffffffu, ab, o);
        pl  += __shfl_xor_sync(0xffffffffu, pl, o);
    }
    if (lane == 0) { red[0][wid] = ce; red[1][wid] = sem; red[2][wid] = ab; red[3][wid] = pl; }
    __syncthreads();
    if (tid == 0) {
        float tce = 0.f, tsem = 0.f, tab = 0.f, tpl = 0.f;
#pragma unroll
        for (int w = 0; w < 8; w++) {
            tce += red[0][w]; tsem += red[1][w]; tab += red[2][w]; tpl += red[3][w];
        }
        const float invB  = 1.0f / (float)B_ROWS;
        const float invN2 = 1.0f / ((float)NN * (float)NN);
        const float l_task   = tce * invB;
        const float l_sparse = tab * invN2;
        const float l_sem    = (tpl - tsem) * invN2;
        out[0] = 1.0f * l_task + 0.01f * l_sparse + 0.1f * l_sem;
    }
}

// ---------------- launch ----------------
extern "C" void kernel_launch(void* const* d_in, const int* in_sizes, int n_in,
                              void* d_out, int out_size) {
    const float* pred = nullptr; const void* tgt = nullptr;
    const float* adj  = nullptr; const float* emb = nullptr;
    for (int i = 0; i < n_in; i++) {
        switch (in_sizes[i]) {
            case B_ROWS * C_CLS:     pred = (const float*)d_in[i]; break;
            case B_ROWS:             tgt  = d_in[i];               break;
            case NN * NN:            adj  = (const float*)d_in[i]; break;
            case NN * DD:            emb  = (const float*)d_in[i]; break;
            default: break;
        }
    }
    float* out = (float*)d_out;
    (void)out_size;

    rdl_probe<<<1, 1024>>>((const int*)tgt);
    rdl_ce<<<B_ROWS / 16, 512>>>(pred, tgt);
    rdl_norm<<<NN / 32, 256>>>(emb);
    cudaFuncSetAttribute(rdl_main, cudaFuncAttributeMaxDynamicSharedMemorySize, SMEM_BYTES);
    rdl_main<<<PCTA, THREADS, SMEM_BYTES>>>(adj);
    rdl_combine<<<1, 256>>>(out);
}